// round 2
// baseline (speedup 1.0000x reference)
#include <cuda_runtime.h>
#include <math.h>

#define NB 16
#define NC 64
#define NH 128
#define NW 128
#define NM 16
#define PI2 6.283185307179586f

// ---------------- scratch (no allocations allowed) ----------------
__device__ float2 d_X [NB*NC*256];        // forward modes  [b,i][k*16+l]
__device__ float2 d_Y [NB*NC*256];        // mixed modes    [b,o][k*16+l]
__device__ float2 d_Z1[NB*NC*NH*NM];      // inverse stage1 [b,o][h][l]
__device__ float2 d_Wt[256*64*64];        // transposed weights [kl][i*64+o]
__device__ float  d_proj[NB*NC];          // temb projection

// ---------------- temb projection: proj[b,c] = silu(t) @ temb_w.T + b ----
__global__ void k_proj(const float* __restrict__ temb,
                       const float* __restrict__ twm,
                       const float* __restrict__ tbv) {
    __shared__ float s_silu[512];
    int b = blockIdx.x, c = threadIdx.x;   // 64 threads
    for (int j = c; j < 512; j += 64) {
        float v = temb[b*512 + j];
        s_silu[j] = v / (1.f + __expf(-v));
    }
    __syncthreads();
    float acc = tbv[c];
    #pragma unroll 8
    for (int j = 0; j < 512; j++) acc += s_silu[j] * twm[c*512 + j];
    d_proj[b*64 + c] = acc;
}

// ---------------- weight transpose: [i,o,k,l] -> [kl][i*64+o] ------------
__global__ void k_wt(const float* __restrict__ wr, const float* __restrict__ wi) {
    __shared__ float tr[32][33], ti[32][33];
    int kl0 = blockIdx.x * 32, io0 = blockIdx.y * 32;
    for (int r = threadIdx.y; r < 32; r += 8) {
        tr[r][threadIdx.x] = wr[(io0 + r)*256 + kl0 + threadIdx.x];
        ti[r][threadIdx.x] = wi[(io0 + r)*256 + kl0 + threadIdx.x];
    }
    __syncthreads();
    for (int r = threadIdx.y; r < 32; r += 8) {
        d_Wt[(kl0 + r)*4096 + io0 + threadIdx.x] =
            make_float2(tr[threadIdx.x][r], ti[threadIdx.x][r]);
    }
}

// ---------------- forward truncated DFT (both stages fused) --------------
// X[b,i,k,l] = (1/128) * sum_{h,w} x[b,i,h,w] e^{-2pi i (k h + l w)/128}
#define FWD_SMEM (128*129*4 + 16*129*8 + 2048*8)
__global__ void k_fwd(const float* __restrict__ x) {
    extern __shared__ float sm[];
    float*  xs = sm;                         // [128][129]
    float2* A1 = (float2*)(sm + 128*129);    // [16][129]  (pitch 129 for banks)
    float2* TW = A1 + 16*129;                // [128 w][16 l] : e^{-i 2pi l w/128}
    int t  = threadIdx.x;                    // 256 threads
    int bi = blockIdx.x;                     // b*64+i

    for (int idx = t; idx < 2048; idx += 256) {
        int w = idx >> 4, l = idx & 15;
        float s, c;
        sincosf(PI2 * (float)((l*w) & 127) * (1.f/128.f), &s, &c);
        TW[idx] = make_float2(c, -s);
    }
    const float* xp = x + (size_t)bi * (NH*NW);
    for (int i = t; i < NH*NW; i += 256)
        xs[(i >> 7)*129 + (i & 127)] = xp[i];
    __syncthreads();

    // stage 1 (over w): A1[l,h] = sum_w x[h,w] e^{-i 2pi l w/128}
    {
        int h = t & 127, lb = (t >> 7) * 8;
        float sr[8], si[8];
        #pragma unroll
        for (int j = 0; j < 8; j++) { sr[j] = 0.f; si[j] = 0.f; }
        const float* xrow = xs + h*129;
        for (int w = 0; w < 128; w++) {
            float xv = xrow[w];
            const float2* twp = TW + w*16 + lb;
            #pragma unroll
            for (int j = 0; j < 8; j++) {
                float2 e = twp[j];
                sr[j] += xv * e.x;
                si[j] += xv * e.y;
            }
        }
        #pragma unroll
        for (int j = 0; j < 8; j++)
            A1[(lb + j)*129 + h] = make_float2(sr[j], si[j]);
    }
    __syncthreads();

    // stage 2 (over h): X[k,l] = (1/128) sum_h A1[l,h] e^{-i 2pi k h/128}
    {
        int k = t >> 4, l = t & 15;
        float xr = 0.f, xi = 0.f;
        for (int h2 = 0; h2 < 128; h2++) {
            float2 a = A1[l*129 + h2];
            float2 e = TW[((k*h2) & 127)*16 + 1];   // e^{-i 2pi (k h)/128}
            xr += a.x*e.x - a.y*e.y;
            xi += a.x*e.y + a.y*e.x;
        }
        d_X[bi*256 + t] = make_float2(xr * (1.f/128.f), xi * (1.f/128.f));
    }
}

// ---------------- per-mode channel mixing --------------------------------
// Y[b,o,kl] = sum_i X[b,i,kl] * W[i,o,kl]   (complex)
__global__ void k_mix() {
    __shared__ float2 Ws[4096];     // [i*64+o]
    __shared__ float2 Xs[1024];     // [b*64+i]
    int kl = blockIdx.x, t = threadIdx.x;   // 256 threads
    for (int idx = t; idx < 4096; idx += 256) Ws[idx] = d_Wt[kl*4096 + idx];
    for (int idx = t; idx < 1024; idx += 256) {
        int b = idx >> 6, i = idx & 63;
        Xs[idx] = d_X[(b*64 + i)*256 + kl];
    }
    __syncthreads();
    int o = t & 63, bq = t >> 6;
    #pragma unroll
    for (int j = 0; j < 4; j++) {
        int b = bq*4 + j;
        float yr = 0.f, yi = 0.f;
        #pragma unroll 8
        for (int i = 0; i < 64; i++) {
            float2 xv = Xs[b*64 + i];
            float2 wv = Ws[i*64 + o];
            yr += xv.x*wv.x - xv.y*wv.y;
            yi += xv.x*wv.y + xv.y*wv.x;
        }
        d_Y[(b*64 + o)*256 + kl] = make_float2(yr, yi);
    }
}

// ---------------- inverse stage 1 (over k) -------------------------------
// Z1[b,o,h,l] = (c_l/128) sum_k Y[b,o,k,l] e^{+i 2pi k h/128},  c_0=1 else 2
__global__ void k_invh() {
    __shared__ float2 Ys[256];
    __shared__ float2 twd[128];
    int t = threadIdx.x;                 // 256 threads
    int bo = blockIdx.x;                 // b*64+o
    if (t < 128) {
        float s, c; sincosf(PI2 * t * (1.f/128.f), &s, &c);
        twd[t] = make_float2(c, s);
    }
    Ys[t] = d_Y[bo*256 + t];
    __syncthreads();
    #pragma unroll
    for (int rep = 0; rep < 8; rep++) {
        int idx = rep*256 + t;
        int h = idx >> 4, l = idx & 15;
        float zr = 0.f, zi = 0.f;
        #pragma unroll
        for (int k = 0; k < 16; k++) {
            float2 y = Ys[k*16 + l];
            float2 e = twd[(k*h) & 127];
            zr += y.x*e.x - y.y*e.y;
            zi += y.x*e.y + y.y*e.x;
        }
        float f = (l == 0 ? 1.f : 2.f) * (1.f/128.f);
        d_Z1[(size_t)bo*2048 + idx] = make_float2(zr*f, zi*f);
    }
}

// ---------------- fused final: inverse stage 2 + bypass GEMM + GELU + proj
#define OUT_SMEM (64*32*16 + 64*64*4 + 64*16*8 + 128*8 + 128*4)
__global__ void k_out(const float* __restrict__ x, const float* __restrict__ bw,
                      const float* __restrict__ bb, float* __restrict__ out) {
    extern __shared__ float sm[];
    float4* xs4 = (float4*)sm;               // x tile [i][w/4]  64*32 float4
    float*  bwT = (float*)(xs4 + 64*32);     // bypass_w^T [i][o] 64*64
    float2* z1s = (float2*)(bwT + 64*64);    // [o][l] 64*16
    float2* twd = z1s + 64*16;               // e^{+i 2pi t/128}, 128
    float*  bbp = (float*)(twd + 128);       // [0..63]=bias, [64..127]=proj

    int t = threadIdx.x;                     // 256 threads
    int b = blockIdx.x >> 7, h = blockIdx.x & 127;

    if (t < 128) {
        float s, c; sincosf(PI2 * t * (1.f/128.f), &s, &c);
        twd[t] = make_float2(c, s);
    }
    for (int idx = t; idx < 4096; idx += 256)
        bwT[(idx & 63)*64 + (idx >> 6)] = bw[idx];       // [o][i] -> [i][o]
    if (t < 64) bbp[t] = bb[t];
    else if (t < 128) bbp[t] = d_proj[b*64 + (t - 64)];
    for (int idx = t; idx < 1024; idx += 256) {
        int o = idx >> 4;
        z1s[idx] = d_Z1[((size_t)(b*64 + o)*128 + h)*16 + (idx & 15)];
    }
    const float4* xg = (const float4*)x;
    for (int idx = t; idx < 64*32; idx += 256) {
        int i = idx >> 5, w4 = idx & 31;
        xs4[idx] = xg[((size_t)(b*64 + i)*128 + h)*32 + w4];
    }
    __syncthreads();

    int to = t >> 4, twi = t & 15;           // o base = to*4, w base = twi*8
    float acc[4][8];
    #pragma unroll
    for (int a = 0; a < 4; a++)
        #pragma unroll
        for (int c2 = 0; c2 < 8; c2++) acc[a][c2] = 0.f;

    // bypass GEMM: acc[o,w] += bw[o,i] * x[i,w]
    const float4* bw4 = (const float4*)bwT;
    #pragma unroll 8
    for (int k = 0; k < 64; k++) {
        float4 wv = bw4[k*16 + to];
        float4 x0 = xs4[k*32 + twi*2];
        float4 x1 = xs4[k*32 + twi*2 + 1];
        float xw[8] = {x0.x, x0.y, x0.z, x0.w, x1.x, x1.y, x1.z, x1.w};
        float ww[4] = {wv.x, wv.y, wv.z, wv.w};
        #pragma unroll
        for (int a = 0; a < 4; a++)
            #pragma unroll
            for (int c2 = 0; c2 < 8; c2++)
                acc[a][c2] += ww[a] * xw[c2];
    }
    // inverse stage 2 (over l): spec = sum_l Re(Z1[o,l] e^{+i 2pi l w/128})
    #pragma unroll
    for (int l = 0; l < 16; l++) {
        float2 z[4];
        #pragma unroll
        for (int a = 0; a < 4; a++) z[a] = z1s[(to*4 + a)*16 + l];
        #pragma unroll
        for (int c2 = 0; c2 < 8; c2++) {
            int w = twi*8 + c2;
            float2 e = twd[(l*w) & 127];
            #pragma unroll
            for (int a = 0; a < 4; a++)
                acc[a][c2] += z[a].x*e.x - z[a].y*e.y;
        }
    }
    // epilogue: + bias, exact GELU, + proj
    float4* og = (float4*)out;
    #pragma unroll
    for (int a = 0; a < 4; a++) {
        int o = to*4 + a;
        float bias = bbp[o], pr = bbp[64 + o];
        float vals[8];
        #pragma unroll
        for (int c2 = 0; c2 < 8; c2++) {
            float v = acc[a][c2] + bias;
            vals[c2] = 0.5f * v * (1.f + erff(v * 0.70710678118f)) + pr;
        }
        size_t base = ((size_t)(b*64 + o)*128 + h)*32 + twi*2;
        og[base]     = make_float4(vals[0], vals[1], vals[2], vals[3]);
        og[base + 1] = make_float4(vals[4], vals[5], vals[6], vals[7]);
    }
}

// ---------------- launcher ----------------------------------------------
extern "C" void kernel_launch(void* const* d_in, const int* in_sizes, int n_in,
                              void* d_out, int out_size) {
    const float* x    = (const float*)d_in[0];
    const float* temb = (const float*)d_in[1];
    const float* wr   = (const float*)d_in[2];
    const float* wi   = (const float*)d_in[3];
    const float* bw   = (const float*)d_in[4];
    const float* bb   = (const float*)d_in[5];
    const float* twm  = (const float*)d_in[6];
    const float* tbv  = (const float*)d_in[7];
    float* out = (float*)d_out;

    cudaFuncSetAttribute(k_fwd, cudaFuncAttributeMaxDynamicSharedMemorySize, FWD_SMEM);
    cudaFuncSetAttribute(k_out, cudaFuncAttributeMaxDynamicSharedMemorySize, OUT_SMEM);

    k_proj<<<NB, 64>>>(temb, twm, tbv);
    k_wt  <<<dim3(8, 128), dim3(32, 8)>>>(wr, wi);
    k_fwd <<<NB*NC, 256, FWD_SMEM>>>(x);
    k_mix <<<256, 256>>>();
    k_invh<<<NB*NC, 256>>>();
    k_out <<<NB*NH, 256, OUT_SMEM>>>(x, bw, bb, out);
}

// round 3
// speedup vs baseline: 1.6410x; 1.6410x over previous
#include <cuda_runtime.h>
#include <math.h>

#define NB 16
#define NC 64
#define NH 128
#define NW 128
#define NM 16
#define PI2 6.283185307179586f

// ---------------- scratch (no allocations allowed) ----------------
__device__ float2 d_X [NB*NC*256];        // forward modes  [b,i][k*16+l]
__device__ float2 d_Y [NB*NC*256];        // mixed modes    [b,o][k*16+l]
__device__ float2 d_Z1[NB*NC*NH*NM];      // inverse stage1 [b,o][h][l]
__device__ float2 d_Wt[256*64*64];        // transposed weights [kl][i*64+o]
__device__ float  d_proj[NB*NC];          // temb projection

// ---------------- helpers -----------------------------------------------
__device__ __forceinline__ unsigned tf32u(float f) {
    unsigned r; asm("cvt.rna.tf32.f32 %0, %1;" : "=r"(r) : "f"(f)); return r;
}
__device__ __forceinline__ float tf32f(float f) {
    return __uint_as_float(tf32u(f));
}
__device__ __forceinline__ void mma_tf32(float* c,
    unsigned a0, unsigned a1, unsigned a2, unsigned a3,
    unsigned b0, unsigned b1) {
    asm volatile(
        "mma.sync.aligned.m16n8k8.row.col.f32.tf32.tf32.f32 "
        "{%0,%1,%2,%3}, {%4,%5,%6,%7}, {%8,%9}, {%0,%1,%2,%3};"
        : "+f"(c[0]), "+f"(c[1]), "+f"(c[2]), "+f"(c[3])
        : "r"(a0), "r"(a1), "r"(a2), "r"(a3), "r"(b0), "r"(b1));
}

// ---------------- temb projection: proj[b,c] = silu(t) @ temb_w.T + b ----
__global__ void k_proj(const float* __restrict__ temb,
                       const float* __restrict__ twm,
                       const float* __restrict__ tbv) {
    __shared__ float s_silu[512];
    int b = blockIdx.x, c = threadIdx.x;   // 64 threads
    for (int j = c; j < 512; j += 64) {
        float v = temb[b*512 + j];
        s_silu[j] = v / (1.f + __expf(-v));
    }
    __syncthreads();
    float acc = tbv[c];
    #pragma unroll 8
    for (int j = 0; j < 512; j++) acc += s_silu[j] * twm[c*512 + j];
    d_proj[b*64 + c] = acc;
}

// ---------------- weight transpose: [i,o,k,l] -> [kl][i*64+o] ------------
__global__ void k_wt(const float* __restrict__ wr, const float* __restrict__ wi) {
    __shared__ float tr[32][33], ti[32][33];
    int kl0 = blockIdx.x * 32, io0 = blockIdx.y * 32;
    for (int r = threadIdx.y; r < 32; r += 8) {
        tr[r][threadIdx.x] = wr[(io0 + r)*256 + kl0 + threadIdx.x];
        ti[r][threadIdx.x] = wi[(io0 + r)*256 + kl0 + threadIdx.x];
    }
    __syncthreads();
    for (int r = threadIdx.y; r < 32; r += 8) {
        d_Wt[(kl0 + r)*4096 + io0 + threadIdx.x] =
            make_float2(tr[threadIdx.x][r], ti[threadIdx.x][r]);
    }
}

// ---------------- forward truncated DFT ----------------------------------
// Stage 1 (tensor cores): A1[h, (l,c)] = sum_w x[h,w] * E[w, (l,c)]
//   where E[w,2l]=cos(2pi lw/128), E[w,2l+1]=-sin(...)  (e^{-i...})
// Stage 2 (scalar): X[k,l] = (1/128) sum_h A1[l,h] e^{-i 2pi k h/128}
#define XP 132   // x smem pitch (== 4 mod 32 -> conflict-free A-frag loads)
#define EP 40    // E smem pitch (== 8 mod 32 -> conflict-free B-frag loads)
#define FWD_SMEM (128*XP*4 + 128*EP*4 + 16*129*8 + 128*8)
__global__ __launch_bounds__(256) void k_fwd(const float* __restrict__ x) {
    extern __shared__ float sm[];
    float*  xs  = sm;                          // [128 h][XP] (tf32 bits)
    float*  Es  = xs + 128*XP;                 // [128 w][EP] (tf32 bits)
    float2* A1  = (float2*)(Es + 128*EP);      // [16 l][129 h]
    float2* twd = A1 + 16*129;                 // e^{-i 2pi m/128}, 128

    int t  = threadIdx.x;                      // 256 threads = 8 warps
    int bi = blockIdx.x;                       // b*64+i

    const float4* xg = (const float4*)(x + (size_t)bi * 16384);
    for (int idx = t; idx < 4096; idx += 256) {
        int hh = idx >> 5, w4 = idx & 31;
        float4 v = xg[hh*32 + w4];
        int base = hh*XP + w4*4;
        xs[base+0] = tf32f(v.x); xs[base+1] = tf32f(v.y);
        xs[base+2] = tf32f(v.z); xs[base+3] = tf32f(v.w);
    }
    for (int idx = t; idx < 2048; idx += 256) {
        int w = idx >> 4, l = idx & 15;
        float s, c;
        sincosf(PI2 * (float)((l*w) & 127) * (1.f/128.f), &s, &c);
        Es[w*EP + 2*l]     = tf32f(c);
        Es[w*EP + 2*l + 1] = tf32f(-s);
    }
    if (t < 128) {
        float s, c; sincosf(PI2 * t * (1.f/128.f), &s, &c);
        twd[t] = make_float2(c, -s);
    }
    __syncthreads();

    int lane = t & 31, warp = t >> 5;
    int qr = lane >> 2, qc = lane & 3;
    const unsigned* xsu = (const unsigned*)xs;
    const unsigned* Esu = (const unsigned*)Es;

    // GEMM1: M=128 (h, warp*16), N=32 (l,c), K=128 (w)
    {
        int m0 = warp * 16;
        float acc[4][4];
        #pragma unroll
        for (int a = 0; a < 4; a++)
            #pragma unroll
            for (int j = 0; j < 4; j++) acc[a][j] = 0.f;
        #pragma unroll
        for (int kk = 0; kk < 16; kk++) {
            int k0 = kk * 8;
            unsigned a0 = xsu[(m0+qr  )*XP + k0+qc  ];
            unsigned a1 = xsu[(m0+qr+8)*XP + k0+qc  ];
            unsigned a2 = xsu[(m0+qr  )*XP + k0+qc+4];
            unsigned a3 = xsu[(m0+qr+8)*XP + k0+qc+4];
            #pragma unroll
            for (int nt = 0; nt < 4; nt++) {
                unsigned b0 = Esu[(k0+qc  )*EP + nt*8 + qr];
                unsigned b1 = Esu[(k0+qc+4)*EP + nt*8 + qr];
                mma_tf32(acc[nt], a0, a1, a2, a3, b0, b1);
            }
        }
        // C frag: rows m0+qr / m0+qr+8, cols nt*8 + 2*qc (+1) -> (l = nt*4+qc, r/i)
        #pragma unroll
        for (int nt = 0; nt < 4; nt++) {
            int l = nt*4 + qc;
            A1[l*129 + m0 + qr    ] = make_float2(acc[nt][0], acc[nt][1]);
            A1[l*129 + m0 + qr + 8] = make_float2(acc[nt][2], acc[nt][3]);
        }
    }
    __syncthreads();

    // Stage 2: X[k,l] = (1/128) sum_h A1[l,h] e^{-i 2pi k h/128}
    {
        int k = t >> 4, l = t & 15;
        float xr = 0.f, xi = 0.f;
        for (int h2 = 0; h2 < 128; h2++) {
            float2 a = A1[l*129 + h2];
            float2 e = twd[(k*h2) & 127];
            xr += a.x*e.x - a.y*e.y;
            xi += a.x*e.y + a.y*e.x;
        }
        d_X[bi*256 + t] = make_float2(xr * (1.f/128.f), xi * (1.f/128.f));
    }
}

// ---------------- per-mode channel mixing --------------------------------
// Y[b,o,kl] = sum_i X[b,i,kl] * W[i,o,kl]   (complex)
__global__ void k_mix() {
    __shared__ float2 Ws[4096];     // [i*64+o]
    __shared__ float2 Xs[1024];     // [b*64+i]
    int kl = blockIdx.x, t = threadIdx.x;   // 256 threads
    for (int idx = t; idx < 4096; idx += 256) Ws[idx] = d_Wt[kl*4096 + idx];
    for (int idx = t; idx < 1024; idx += 256) {
        int b = idx >> 6, i = idx & 63;
        Xs[idx] = d_X[(b*64 + i)*256 + kl];
    }
    __syncthreads();
    int o = t & 63, bq = t >> 6;
    #pragma unroll
    for (int j = 0; j < 4; j++) {
        int b = bq*4 + j;
        float yr = 0.f, yi = 0.f;
        #pragma unroll 8
        for (int i = 0; i < 64; i++) {
            float2 xv = Xs[b*64 + i];
            float2 wv = Ws[i*64 + o];
            yr += xv.x*wv.x - xv.y*wv.y;
            yi += xv.x*wv.y + xv.y*wv.x;
        }
        d_Y[(b*64 + o)*256 + kl] = make_float2(yr, yi);
    }
}

// ---------------- inverse stage 1 (over k) -------------------------------
// Z1[b,o,h,l] = (c_l/128) sum_k Y[b,o,k,l] e^{+i 2pi k h/128},  c_0=1 else 2
__global__ void k_invh() {
    __shared__ float2 Ys[256];
    __shared__ float2 twd[128];
    int t = threadIdx.x;                 // 256 threads
    int bo = blockIdx.x;                 // b*64+o
    if (t < 128) {
        float s, c; sincosf(PI2 * t * (1.f/128.f), &s, &c);
        twd[t] = make_float2(c, s);
    }
    Ys[t] = d_Y[bo*256 + t];
    __syncthreads();
    #pragma unroll
    for (int rep = 0; rep < 8; rep++) {
        int idx = rep*256 + t;
        int h = idx >> 4, l = idx & 15;
        float zr = 0.f, zi = 0.f;
        #pragma unroll
        for (int k = 0; k < 16; k++) {
            float2 y = Ys[k*16 + l];
            float2 e = twd[(k*h) & 127];
            zr += y.x*e.x - y.y*e.y;
            zi += y.x*e.y + y.y*e.x;
        }
        float f = (l == 0 ? 1.f : 2.f) * (1.f/128.f);
        d_Z1[(size_t)bo*2048 + idx] = make_float2(zr*f, zi*f);
    }
}

// ---------------- fused final (tensor cores) -----------------------------
// Per (b,h): C[64o, 128w] = A[64, 96] @ B[96, 128]
//   A = [ bw(64x64) | Zr(64x16) | Zi(64x16) ]
//   B = [ x(64x128) ; cos(16x128) ; -sin(16x128) ]   (e^{+i 2pi l w/128})
// epilogue: v = C + bias; out = gelu(v) + proj
#define BP 136   // B pitch (== 8 mod 32)
#define AP 100   // A pitch (== 4 mod 32)
#define OUT_SMEM (96*BP*4 + 64*AP*4 + 128*4)
__global__ __launch_bounds__(256) void k_out(const float* __restrict__ x,
                                             const float* __restrict__ bw,
                                             const float* __restrict__ bb,
                                             float* __restrict__ out) {
    extern __shared__ float sm[];
    float* Bs  = sm;               // [96][BP]
    float* As  = Bs + 96*BP;       // [64][AP]
    float* bbp = As + 64*AP;       // [0..63]=bias, [64..127]=proj

    int t = threadIdx.x;           // 256 threads = 8 warps
    int b = blockIdx.x >> 7, h = blockIdx.x & 127;

    // B rows 0..63: x[b,i,h,:]
    for (int idx = t; idx < 64*32; idx += 256) {
        int i = idx >> 5, w4 = idx & 31;
        float4 v = ((const float4*)x)[ (((size_t)(b*64+i))*128 + h)*32 + w4 ];
        int base = i*BP + w4*4;
        Bs[base+0] = tf32f(v.x); Bs[base+1] = tf32f(v.y);
        Bs[base+2] = tf32f(v.z); Bs[base+3] = tf32f(v.w);
    }
    // B rows 64..95: twiddles
    for (int idx = t; idx < 2048; idx += 256) {
        int l = idx >> 7, w = idx & 127;
        float s, c;
        sincosf(PI2 * (float)((l*w) & 127) * (1.f/128.f), &s, &c);
        Bs[(64+l)*BP + w] = tf32f(c);
        Bs[(80+l)*BP + w] = tf32f(-s);
    }
    // A cols 0..63: bw[o][i]
    for (int idx = t; idx < 4096; idx += 256) {
        int o = idx >> 6, i = idx & 63;
        As[o*AP + i] = tf32f(bw[idx]);
    }
    // A cols 64..95: Zr | Zi
    for (int idx = t; idx < 1024; idx += 256) {
        int o = idx >> 4, l = idx & 15;
        float2 z = d_Z1[ ((size_t)(b*64+o))*2048 + h*16 + l ];
        As[o*AP + 64 + l] = tf32f(z.x);
        As[o*AP + 80 + l] = tf32f(z.y);
    }
    if (t < 64) bbp[t] = bb[t];
    else if (t < 128) bbp[t] = d_proj[b*64 + (t - 64)];
    __syncthreads();

    int lane = t & 31, warp = t >> 5;
    int m0 = (warp & 3) * 16, n0 = (warp >> 2) * 64;
    int qr = lane >> 2, qc = lane & 3;
    const unsigned* Asu = (const unsigned*)As;
    const unsigned* Bsu = (const unsigned*)Bs;

    float acc[8][4];
    #pragma unroll
    for (int nt = 0; nt < 8; nt++)
        #pragma unroll
        for (int j = 0; j < 4; j++) acc[nt][j] = 0.f;

    #pragma unroll
    for (int kk = 0; kk < 12; kk++) {
        int k0 = kk * 8;
        unsigned a0 = Asu[(m0+qr  )*AP + k0+qc  ];
        unsigned a1 = Asu[(m0+qr+8)*AP + k0+qc  ];
        unsigned a2 = Asu[(m0+qr  )*AP + k0+qc+4];
        unsigned a3 = Asu[(m0+qr+8)*AP + k0+qc+4];
        #pragma unroll
        for (int nt = 0; nt < 8; nt++) {
            unsigned b0 = Bsu[(k0+qc  )*BP + n0 + nt*8 + qr];
            unsigned b1 = Bsu[(k0+qc+4)*BP + n0 + nt*8 + qr];
            mma_tf32(acc[nt], a0, a1, a2, a3, b0, b1);
        }
    }

    // epilogue: rows m0+qr (c0,c1) and m0+qr+8 (c2,c3); cols n0+nt*8+2*qc(+1)
    #pragma unroll
    for (int nt = 0; nt < 8; nt++) {
        #pragma unroll
        for (int half = 0; half < 2; half++) {
            int o = m0 + qr + half*8;
            float bias = bbp[o], pr = bbp[64 + o];
            float v0 = acc[nt][half*2 + 0] + bias;
            float v1 = acc[nt][half*2 + 1] + bias;
            v0 = 0.5f * v0 * (1.f + erff(v0 * 0.70710678118f)) + pr;
            v1 = 0.5f * v1 * (1.f + erff(v1 * 0.70710678118f)) + pr;
            int w = n0 + nt*8 + qc*2;
            *(float2*)(out + (((size_t)(b*64+o))*128 + h)*128 + w) =
                make_float2(v0, v1);
        }
    }
}

// ---------------- launcher ----------------------------------------------
extern "C" void kernel_launch(void* const* d_in, const int* in_sizes, int n_in,
                              void* d_out, int out_size) {
    const float* x    = (const float*)d_in[0];
    const float* temb = (const float*)d_in[1];
    const float* wr   = (const float*)d_in[2];
    const float* wi   = (const float*)d_in[3];
    const float* bw   = (const float*)d_in[4];
    const float* bb   = (const float*)d_in[5];
    const float* twm  = (const float*)d_in[6];
    const float* tbv  = (const float*)d_in[7];
    float* out = (float*)d_out;

    cudaFuncSetAttribute(k_fwd, cudaFuncAttributeMaxDynamicSharedMemorySize, FWD_SMEM);
    cudaFuncSetAttribute(k_out, cudaFuncAttributeMaxDynamicSharedMemorySize, OUT_SMEM);

    k_proj<<<NB, 64>>>(temb, twm, tbv);
    k_wt  <<<dim3(8, 128), dim3(32, 8)>>>(wr, wi);
    k_fwd <<<NB*NC, 256, FWD_SMEM>>>(x);
    k_mix <<<256, 256>>>();
    k_invh<<<NB*NC, 256>>>();
    k_out <<<NB*NH, 256, OUT_SMEM>>>(x, bw, bb, out);
}